// round 10
// baseline (speedup 1.0000x reference)
#include <cuda_runtime.h>
#include <cuda_bf16.h>
#include <math.h>
#include <stdint.h>
#include <string.h>

#define NROWS 8192
#define H 512
#define CC 100
#define RR 69
#define PP 69
#define EPSV 1e-8f
#define NPAIRS (CC * CC)

typedef unsigned long long ull;

// ---------------- scratch (device globals, no runtime alloc) ----------------
__device__ __nv_bfloat16 g_vcat_hi[(size_t)NROWS * 3 * H];
__device__ __nv_bfloat16 g_vcat_lo[(size_t)NROWS * 3 * H];
__device__ __nv_bfloat16 g_h_hi[(size_t)NROWS * H];
__device__ __nv_bfloat16 g_h_lo[(size_t)NROWS * H];
__device__ float         g_vf[(size_t)NROWS * H];
__device__ __nv_bfloat16 g_rf_hi[(size_t)NROWS * 2 * H];
__device__ __nv_bfloat16 g_rf_lo[(size_t)NROWS * 2 * H];
__device__ float         g_h2[(size_t)NROWS * H];
__device__ __nv_bfloat16 g_w1t_hi[(size_t)H * 3 * H];
__device__ __nv_bfloat16 g_w1t_lo[(size_t)H * 3 * H];
__device__ __nv_bfloat16 g_w2t_hi[(size_t)H * H];
__device__ __nv_bfloat16 g_w2t_lo[(size_t)H * H];
__device__ __nv_bfloat16 g_rw1t_hi[(size_t)H * 2 * H];
__device__ __nv_bfloat16 g_rw1t_lo[(size_t)H * 2 * H];
// pair-sort scratch
__device__ int g_hist[NPAIRS];
__device__ int g_offs[NPAIRS];
__device__ int g_perm[NROWS];

// ---------------- helpers ----------------
__device__ __forceinline__ void split_bf16(float v, __nv_bfloat16& hi, __nv_bfloat16& lo) {
    hi = __float2bfloat16(v);
    lo = __float2bfloat16(v - __bfloat162float(hi));
}
__device__ __forceinline__ uint16_t bf_bits(__nv_bfloat16 h) {
    uint16_t b; memcpy(&b, &h, 2); return b;
}
__device__ __forceinline__ uint32_t smem_u32(const void* p) {
    return (uint32_t)__cvta_generic_to_shared(p);
}
__device__ __forceinline__ void cp_async16(uint32_t smem_dst, const void* gmem_src) {
    asm volatile("cp.async.cg.shared.global [%0], [%1], 16;" :: "r"(smem_dst), "l"(gmem_src) : "memory");
}
__device__ __forceinline__ void cp_commit() {
    asm volatile("cp.async.commit_group;" ::: "memory");
}
#define CP_WAIT(n) asm volatile("cp.async.wait_group %0;" :: "n"(n) : "memory")

__device__ __forceinline__ void mma16816(float* d, const uint32_t* a, const uint32_t* b) {
    asm volatile(
        "mma.sync.aligned.m16n8k16.row.col.f32.bf16.bf16.f32 "
        "{%0,%1,%2,%3},{%4,%5,%6,%7},{%8,%9},{%0,%1,%2,%3};"
        : "+f"(d[0]), "+f"(d[1]), "+f"(d[2]), "+f"(d[3])
        : "r"(a[0]), "r"(a[1]), "r"(a[2]), "r"(a[3]), "r"(b[0]), "r"(b[1]));
}

// ---------------- pair sort kernels ----------------
__global__ void pair_hist_kernel(const int* __restrict__ scats,
                                 const int* __restrict__ ocats) {
    int n = blockIdx.x * blockDim.x + threadIdx.x;
    if (n < NROWS) atomicAdd(&g_hist[scats[n] * CC + ocats[n]], 1);
}

__global__ __launch_bounds__(1024)
void pair_scan_kernel() {       // single block
    __shared__ int part[1024];
    const int tid = threadIdx.x;
    const int per = (NPAIRS + 1023) / 1024;    // 10
    const int base = tid * per;
    int sum = 0;
    for (int i = 0; i < per; i++) {
        int idx = base + i;
        if (idx < NPAIRS) sum += g_hist[idx];
    }
    part[tid] = sum;
    __syncthreads();
    for (int off = 1; off < 1024; off <<= 1) {
        int v = (tid >= off) ? part[tid - off] : 0;
        __syncthreads();
        part[tid] += v;
        __syncthreads();
    }
    int excl = (tid == 0) ? 0 : part[tid - 1];
    for (int i = 0; i < per; i++) {
        int idx = base + i;
        if (idx < NPAIRS) {
            int c = g_hist[idx];
            g_offs[idx] = excl;
            excl += c;
        }
    }
}

__global__ void pair_scatter_kernel(const int* __restrict__ scats,
                                    const int* __restrict__ ocats) {
    int n = blockIdx.x * blockDim.x + threadIdx.x;
    if (n < NROWS) {
        int p = scats[n] * CC + ocats[n];
        int pos = atomicAdd(&g_offs[p], 1);
        g_perm[pos] = n;
    }
}

// ---------------- concat -> bf16 hi/lo ----------------
__global__ void concat_kernel(const float* __restrict__ s,
                              const float* __restrict__ p,
                              const float* __restrict__ o) {
    size_t idx = (size_t)blockIdx.x * blockDim.x + threadIdx.x;
    size_t total = (size_t)NROWS * 3 * H / 4;
    if (idx >= total) return;
    size_t row = idx / (3 * H / 4);
    size_t col4 = idx % (3 * H / 4);
    const float4* src;
    size_t within;
    if (col4 < H / 4)            { src = (const float4*)s; within = col4; }
    else if (col4 < 2 * (H / 4)) { src = (const float4*)p; within = col4 - H / 4; }
    else                         { src = (const float4*)o; within = col4 - 2 * (H / 4); }
    float4 v = src[row * (H / 4) + within];
    __nv_bfloat16 h0, l0, h1, l1, h2v, l2, h3, l3;
    split_bf16(v.x, h0, l0); split_bf16(v.y, h1, l1);
    split_bf16(v.z, h2v, l2); split_bf16(v.w, h3, l3);
    uint32_t* dh = (uint32_t*)(g_vcat_hi + idx * 4);
    uint32_t* dl = (uint32_t*)(g_vcat_lo + idx * 4);
    dh[0] = (uint32_t)bf_bits(h0) | ((uint32_t)bf_bits(h1) << 16);
    dh[1] = (uint32_t)bf_bits(h2v) | ((uint32_t)bf_bits(h3) << 16);
    dl[0] = (uint32_t)bf_bits(l0) | ((uint32_t)bf_bits(l1) << 16);
    dl[1] = (uint32_t)bf_bits(l2) | ((uint32_t)bf_bits(l3) << 16);
}

// ---------------- weight transpose + split ----------------
__global__ void wtrans_kernel(const float* __restrict__ W,
                              __nv_bfloat16* __restrict__ Thi,
                              __nv_bfloat16* __restrict__ Tlo,
                              int K, int N) {
    size_t idx = (size_t)blockIdx.x * blockDim.x + threadIdx.x;
    size_t total = (size_t)K * N;
    if (idx >= total) return;
    int n = (int)(idx / K);
    int k = (int)(idx % K);
    float v = W[(size_t)k * N + n];
    __nv_bfloat16 hi, lo;
    split_bf16(v, hi, lo);
    Thi[idx] = hi; Tlo[idx] = lo;
}

// ---------------- mma.sync bf16x3 GEMM, 3-stage pipeline ----------------
#define TG_LDS 72
#define TG_STAGES 3
#define TG_STAGE_ELEMS (128 * TG_LDS)
#define TG_SMEM (2 * TG_STAGES * TG_STAGE_ELEMS * 2)   // 110592 B

template<bool WB16, bool WF32, bool RELU>
__global__ __launch_bounds__(256, 2)
void tgemm_kernel(const __nv_bfloat16* __restrict__ Ahi, const __nv_bfloat16* __restrict__ Alo,
                  const __nv_bfloat16* __restrict__ Bhi, const __nv_bfloat16* __restrict__ Blo,
                  const float* __restrict__ bias,
                  __nv_bfloat16* __restrict__ Chi, __nv_bfloat16* __restrict__ Clo,
                  float* __restrict__ Cf32,
                  int K, int Ntot) {
    extern __shared__ __align__(16) __nv_bfloat16 smem[];

    const int tid = threadIdx.x;
    const int wid = tid >> 5;
    const int lane = tid & 31;
    const int g = lane >> 2;
    const int t = lane & 3;
    const int wm = wid & 3;
    const int wn = wid >> 2;
    const int bm = blockIdx.y * 128;
    const int bn = blockIdx.x * 128;

    const int per = K >> 6;
    const int C = 3 * per;

    float acc[2][8][4];
#pragma unroll
    for (int i = 0; i < 2; i++)
#pragma unroll
        for (int j = 0; j < 8; j++)
#pragma unroll
            for (int q = 0; q < 4; q++) acc[i][j][q] = 0.f;

    auto load_chunk = [&](int c, int s) {
        int p = c / per;
        int kc = (c - p * per) << 6;
        const __nv_bfloat16* As = (p == 1) ? Alo : Ahi;
        const __nv_bfloat16* Bs = (p == 2) ? Blo : Bhi;
        uint32_t abase = smem_u32(smem + s * TG_STAGE_ELEMS);
        uint32_t bbase = smem_u32(smem + (TG_STAGES + s) * TG_STAGE_ELEMS);
#pragma unroll
        for (int i = 0; i < 4; i++) {
            int seg = tid + i * 256;
            int row = seg >> 3, sg = seg & 7;
            cp_async16(abase + (row * TG_LDS + sg * 8) * 2,
                       As + (size_t)(bm + row) * K + kc + sg * 8);
        }
#pragma unroll
        for (int i = 0; i < 4; i++) {
            int seg = tid + i * 256;
            int row = seg >> 3, sg = seg & 7;
            cp_async16(bbase + (row * TG_LDS + sg * 8) * 2,
                       Bs + (size_t)(bn + row) * K + kc + sg * 8);
        }
        cp_commit();
    };

    load_chunk(0, 0);
    load_chunk(1, 1);
    load_chunk(2, 2);

    for (int c = 0; c < C; c++) {
        const int s = c % TG_STAGES;
        CP_WAIT(2);
        __syncthreads();

        const __nv_bfloat16* As = smem + s * TG_STAGE_ELEMS;
        const __nv_bfloat16* Bs = smem + (TG_STAGES + s) * TG_STAGE_ELEMS;
#pragma unroll
        for (int ks = 0; ks < 4; ks++) {
            const int k0 = ks * 16;
            uint32_t afrag[2][4];
#pragma unroll
            for (int mt = 0; mt < 2; mt++) {
                int row = wm * 32 + mt * 16 + g;
                const __nv_bfloat16* ar0 = As + (size_t)row * TG_LDS + k0 + 2 * t;
                const __nv_bfloat16* ar1 = As + (size_t)(row + 8) * TG_LDS + k0 + 2 * t;
                afrag[mt][0] = *(const uint32_t*)ar0;
                afrag[mt][1] = *(const uint32_t*)ar1;
                afrag[mt][2] = *(const uint32_t*)(ar0 + 8);
                afrag[mt][3] = *(const uint32_t*)(ar1 + 8);
            }
#pragma unroll
            for (int nt = 0; nt < 8; nt++) {
                int n = wn * 64 + nt * 8 + g;
                const __nv_bfloat16* br = Bs + (size_t)n * TG_LDS + k0 + 2 * t;
                uint32_t bfrag[2];
                bfrag[0] = *(const uint32_t*)br;
                bfrag[1] = *(const uint32_t*)(br + 8);
#pragma unroll
                for (int mt = 0; mt < 2; mt++)
                    mma16816(acc[mt][nt], afrag[mt], bfrag);
            }
        }
        __syncthreads();
        if (c + 3 < C) load_chunk(c + 3, s);
        else cp_commit();
    }

    // epilogue
#pragma unroll
    for (int mt = 0; mt < 2; mt++) {
        int row0 = bm + wm * 32 + mt * 16 + g;
        int row1 = row0 + 8;
#pragma unroll
        for (int nt = 0; nt < 8; nt++) {
            int col = bn + wn * 64 + nt * 8 + 2 * t;
            float2 bv = __ldg((const float2*)(bias + col));
            float v0 = acc[mt][nt][0] + bv.x;
            float v1 = acc[mt][nt][1] + bv.y;
            float v2 = acc[mt][nt][2] + bv.x;
            float v3 = acc[mt][nt][3] + bv.y;
            if (RELU) {
                v0 = fmaxf(v0, 0.f); v1 = fmaxf(v1, 0.f);
                v2 = fmaxf(v2, 0.f); v3 = fmaxf(v3, 0.f);
            }
            if (WF32) {
                *(float2*)(Cf32 + (size_t)row0 * Ntot + col) = make_float2(v0, v1);
                *(float2*)(Cf32 + (size_t)row1 * Ntot + col) = make_float2(v2, v3);
            }
            if (WB16) {
                __nv_bfloat16 h0, l0, h1, l1, h2v, l2, h3, l3;
                split_bf16(v0, h0, l0); split_bf16(v1, h1, l1);
                split_bf16(v2, h2v, l2); split_bf16(v3, h3, l3);
                *(uint32_t*)(Chi + (size_t)row0 * Ntot + col) =
                    (uint32_t)bf_bits(h0) | ((uint32_t)bf_bits(h1) << 16);
                *(uint32_t*)(Chi + (size_t)row1 * Ntot + col) =
                    (uint32_t)bf_bits(h2v) | ((uint32_t)bf_bits(h3) << 16);
                *(uint32_t*)(Clo + (size_t)row0 * Ntot + col) =
                    (uint32_t)bf_bits(l0) | ((uint32_t)bf_bits(l1) << 16);
                *(uint32_t*)(Clo + (size_t)row1 * Ntot + col) =
                    (uint32_t)bf_bits(l2) | ((uint32_t)bf_bits(l3) << 16);
            }
        }
    }
}

// ---------------- FFMA2 SGEMM (final N=69 GEMM) ----------------
__device__ __forceinline__ ull pack2(float lo, float hi) {
    ull r; asm("mov.b64 %0, {%1, %2};" : "=l"(r) : "f"(lo), "f"(hi)); return r;
}
__device__ __forceinline__ void unpack2(ull v, float& lo, float& hi) {
    asm("mov.b64 {%0, %1}, %2;" : "=f"(lo), "=f"(hi) : "l"(v));
}
__device__ __forceinline__ void fma2(ull& d, ull a, ull b) {
    asm("fma.rn.f32x2 %0, %1, %2, %3;" : "=l"(d) : "l"(a), "l"(b), "l"(d));
}

template<bool RELU>
__global__ __launch_bounds__(256)
void sgemm_kernel(const float* __restrict__ A, const float* __restrict__ B,
                  const float* __restrict__ bias, float* __restrict__ C,
                  int M, int Kd, int Nd) {
    __shared__ float As[8][132];
    __shared__ float Bs[8][128];

    const int bm = blockIdx.y * 128;
    const int bn = blockIdx.x * 128;
    const int tid = threadIdx.x;
    const int arow = tid >> 1;
    const int acol = (tid & 1) * 4;
    const int brow = tid >> 5;
    const int bcol = (tid & 31) * 4;
    const int tx = tid & 15;
    const int ty = tid >> 4;

    ull acc2[4][8];
#pragma unroll
    for (int i = 0; i < 4; i++)
#pragma unroll
        for (int j = 0; j < 8; j++) acc2[i][j] = 0ull;

    const bool full_n = (bn + 128 <= Nd);

    for (int k0 = 0; k0 < Kd; k0 += 8) {
        float4 a4 = *(const float4*)(A + (size_t)(bm + arow) * Kd + k0 + acol);
        As[acol + 0][arow] = a4.x;
        As[acol + 1][arow] = a4.y;
        As[acol + 2][arow] = a4.z;
        As[acol + 3][arow] = a4.w;
        if (full_n) {
            *(float4*)&Bs[brow][bcol] =
                *(const float4*)(B + (size_t)(k0 + brow) * Nd + bn + bcol);
        } else {
#pragma unroll
            for (int c = 0; c < 4; c++) {
                int col = bn + bcol + c;
                Bs[brow][bcol + c] = (col < Nd) ? B[(size_t)(k0 + brow) * Nd + col] : 0.f;
            }
        }
        __syncthreads();
#pragma unroll
        for (int k = 0; k < 8; k++) {
            ulonglong2 av0 = *(const ulonglong2*)&As[k][ty * 8];
            ulonglong2 av1 = *(const ulonglong2*)&As[k][ty * 8 + 4];
            ull a2[4] = {av0.x, av0.y, av1.x, av1.y};
            float4 blo = *(const float4*)&Bs[k][tx * 8];
            float4 bhi = *(const float4*)&Bs[k][tx * 8 + 4];
            ull b2[8];
            b2[0] = pack2(blo.x, blo.x); b2[1] = pack2(blo.y, blo.y);
            b2[2] = pack2(blo.z, blo.z); b2[3] = pack2(blo.w, blo.w);
            b2[4] = pack2(bhi.x, bhi.x); b2[5] = pack2(bhi.y, bhi.y);
            b2[6] = pack2(bhi.z, bhi.z); b2[7] = pack2(bhi.w, bhi.w);
#pragma unroll
            for (int i = 0; i < 4; i++)
#pragma unroll
                for (int j = 0; j < 8; j++)
                    fma2(acc2[i][j], a2[i], b2[j]);
        }
        __syncthreads();
    }
#pragma unroll
    for (int i = 0; i < 4; i++) {
        int row_lo = bm + ty * 8 + 2 * i;
        float* c0 = C + (size_t)row_lo * Nd;
        float* c1 = C + (size_t)(row_lo + 1) * Nd;
#pragma unroll
        for (int j = 0; j < 8; j++) {
            int col = bn + tx * 8 + j;
            if (col < Nd) {
                float lo, hi;
                unpack2(acc2[i][j], lo, hi);
                float bv = bias[col];
                lo += bv; hi += bv;
                if (RELU) { lo = fmaxf(lo, 0.f); hi = fmaxf(hi, 0.f); }
                c0[col] = lo;
                c1[col] = hi;
            }
        }
    }
}

// ---------------- streaming online-softmax attention (pair-sorted order) ----------------
#define ACH 8
#define ASTAGES 3
#define A_SMEM ((ASTAGES * ACH * H + H + 4 * ACH + 8) * 4)

__global__ __launch_bounds__(256)
void attn_kernel(const float* __restrict__ vf,
                 const float* __restrict__ rel_base,
                 const int* __restrict__ scats,
                 const int* __restrict__ ocats,
                 __nv_bfloat16* __restrict__ rf_hi,
                 __nv_bfloat16* __restrict__ rf_lo) {
    extern __shared__ float sm[];
    float* ring  = sm;
    float* svf   = ring + ASTAGES * ACH * H;
    float* sdot  = svf + H;
    float* ssq   = sdot + ACH;
    float* sw    = ssq + ACH;
    float* sred  = sw + ACH;
    float* sstat = sred + 8;

    const int n = g_perm[blockIdx.x];          // pair-sorted row order
    const int tid = threadIdx.x;
    const int lane = tid & 31;
    const int warp = tid >> 5;

    const int s = scats[n];
    const int o = ocats[n];
    const float* relp = rel_base + (((size_t)s * RR) * CC + o) * H;

    auto load_chunk = [&](int tc) {
        float* dst = ring + (tc % ASTAGES) * (ACH * H);
#pragma unroll
        for (int i = 0; i < 4; i++) {
            int idx = tid + i * 256;
            int j = idx >> 7;
            int col4 = idx & 127;
            int r = tc * ACH + j;
            if (r < RR)
                cp_async16(smem_u32(dst + j * H + col4 * 4),
                           relp + (size_t)r * CC * H + col4 * 4);
        }
        cp_commit();
    };

    if (tid < 128)
        ((float4*)svf)[tid] = __ldg(&((const float4*)(vf + (size_t)n * H))[tid]);

    load_chunk(0);
    load_chunk(1);
    load_chunk(2);

    __syncthreads();
    {
        float v0 = svf[tid], v1 = svf[tid + 256];
        float part = v0 * v0 + v1 * v1;
#pragma unroll
        for (int off = 16; off > 0; off >>= 1)
            part += __shfl_xor_sync(0xffffffffu, part, off);
        if (lane == 0) sred[warp] = part;
    }

    const int chunks = (RR + ACH - 1) / ACH;
    float acc0 = 0.f, acc1 = 0.f;
    float m_run = -1e30f, s_run = 0.f, vn = 0.f;

    for (int tc = 0; tc < chunks; tc++) {
        CP_WAIT(2);
        __syncthreads();

        {
            const float4* cb4 = (const float4*)(ring + (tc % ASTAGES) * (ACH * H) + warp * H);
            const float4* vf4s = (const float4*)svf;
            float dot = 0.f, sq = 0.f;
#pragma unroll
            for (int i = 0; i < 4; i++) {
                float4 x = cb4[lane + 32 * i];
                float4 v = vf4s[lane + 32 * i];
                dot += x.x * v.x + x.y * v.y + x.z * v.z + x.w * v.w;
                sq  += x.x * x.x + x.y * x.y + x.z * x.z + x.w * x.w;
            }
#pragma unroll
            for (int off = 16; off > 0; off >>= 1) {
                dot += __shfl_down_sync(0xffffffffu, dot, off);
                sq  += __shfl_down_sync(0xffffffffu, sq, off);
            }
            if (lane == 0) { sdot[warp] = dot; ssq[warp] = sq; }
        }
        __syncthreads();

        if (warp == 0) {
            if (tc == 0) {
                float vsq = (lane < 8) ? sred[lane] : 0.f;
#pragma unroll
                for (int off = 4; off > 0; off >>= 1)
                    vsq += __shfl_xor_sync(0xffffffffu, vsq, off);
                vsq = __shfl_sync(0xffffffffu, vsq, 0);
                vn = sqrtf(vsq);
            }
            int r = tc * ACH + lane;
            float c = -1e30f;
            if (lane < ACH && r < RR)
                c = sdot[lane] / fmaxf(vn * sqrtf(ssq[lane]), EPSV);
            float mc = c;
#pragma unroll
            for (int off = 16; off > 0; off >>= 1)
                mc = fmaxf(mc, __shfl_xor_sync(0xffffffffu, mc, off));
            float m_new = fmaxf(m_run, mc);
            float w = (lane < ACH) ? __expf(c - m_new) : 0.f;
            float wsum = w;
#pragma unroll
            for (int off = 16; off > 0; off >>= 1)
                wsum += __shfl_xor_sync(0xffffffffu, wsum, off);
            float scale = __expf(m_run - m_new);
            s_run = s_run * scale + wsum;
            m_run = m_new;
            if (lane < ACH) sw[lane] = w;
            if (lane == 0) sstat[0] = scale;
            if (lane == 0 && tc == chunks - 1) sstat[1] = s_run;
        }
        __syncthreads();

        {
            float scale = sstat[0];
            acc0 *= scale; acc1 *= scale;
            const float* cb = ring + (tc % ASTAGES) * (ACH * H);
#pragma unroll
            for (int r = 0; r < ACH; r++) {
                float wr = sw[r];
                acc0 = fmaf(wr, cb[r * H + tid], acc0);
                acc1 = fmaf(wr, cb[r * H + tid + 256], acc1);
            }
        }
        __syncthreads();

        if (tc + 3 < chunks) load_chunk(tc + 3);
        else cp_commit();
    }

    float inv = 1.f / sstat[1];
    float att0 = acc0 * inv, att1 = acc1 * inv;
    float vv0 = svf[tid], vv1 = svf[tid + 256];

    __nv_bfloat16 h, l;
    size_t base = (size_t)n * 2 * H;
    split_bf16(vv0, h, l);  rf_hi[base + tid] = h;          rf_lo[base + tid] = l;
    split_bf16(vv1, h, l);  rf_hi[base + tid + 256] = h;    rf_lo[base + tid + 256] = l;
    split_bf16(att0, h, l); rf_hi[base + H + tid] = h;      rf_lo[base + H + tid] = l;
    split_bf16(att1, h, l); rf_hi[base + H + tid + 256] = h; rf_lo[base + H + tid + 256] = l;
}

// ---------------- launch ----------------
extern "C" void kernel_launch(void* const* d_in, const int* in_sizes, int n_in,
                              void* d_out, int out_size) {
    if (n_in < 14) return;
    const float* sfeat = (const float*)d_in[0];
    const float* pfeat = (const float*)d_in[1];
    const float* ofeat = (const float*)d_in[2];
    const float* rel   = (const float*)d_in[3];
    const float* w1    = (const float*)d_in[4];
    const float* b1    = (const float*)d_in[5];
    const float* w2    = (const float*)d_in[6];
    const float* b2    = (const float*)d_in[7];
    const float* rw1   = (const float*)d_in[8];
    const float* rb1   = (const float*)d_in[9];
    const float* rw2   = (const float*)d_in[10];
    const float* rb2   = (const float*)d_in[11];
    const int*   scats = (const int*)d_in[12];
    const int*   ocats = (const int*)d_in[13];
    float* out = (float*)d_out;

    __nv_bfloat16 *p_vcat_hi, *p_vcat_lo, *p_h_hi, *p_h_lo;
    __nv_bfloat16 *p_rf_hi, *p_rf_lo;
    __nv_bfloat16 *p_w1t_hi, *p_w1t_lo, *p_w2t_hi, *p_w2t_lo, *p_rw1t_hi, *p_rw1t_lo;
    float *p_vf, *p_h2;
    void* p_hist;
    cudaGetSymbolAddress((void**)&p_vcat_hi, g_vcat_hi);
    cudaGetSymbolAddress((void**)&p_vcat_lo, g_vcat_lo);
    cudaGetSymbolAddress((void**)&p_h_hi, g_h_hi);
    cudaGetSymbolAddress((void**)&p_h_lo, g_h_lo);
    cudaGetSymbolAddress((void**)&p_vf, g_vf);
    cudaGetSymbolAddress((void**)&p_rf_hi, g_rf_hi);
    cudaGetSymbolAddress((void**)&p_rf_lo, g_rf_lo);
    cudaGetSymbolAddress((void**)&p_h2, g_h2);
    cudaGetSymbolAddress((void**)&p_w1t_hi, g_w1t_hi);
    cudaGetSymbolAddress((void**)&p_w1t_lo, g_w1t_lo);
    cudaGetSymbolAddress((void**)&p_w2t_hi, g_w2t_hi);
    cudaGetSymbolAddress((void**)&p_w2t_lo, g_w2t_lo);
    cudaGetSymbolAddress((void**)&p_rw1t_hi, g_rw1t_hi);
    cudaGetSymbolAddress((void**)&p_rw1t_lo, g_rw1t_lo);
    cudaGetSymbolAddress(&p_hist, g_hist);

    const int thr = 256;

    // pair sort (overlaps logically with prep; small kernels)
    cudaMemsetAsync(p_hist, 0, NPAIRS * sizeof(int));
    pair_hist_kernel<<<(NROWS + thr - 1) / thr, thr>>>(scats, ocats);
    pair_scan_kernel<<<1, 1024>>>();
    pair_scatter_kernel<<<(NROWS + thr - 1) / thr, thr>>>(scats, ocats);

    wtrans_kernel<<<(int)(((size_t)3 * H * H + thr - 1) / thr), thr>>>(w1, p_w1t_hi, p_w1t_lo, 3 * H, H);
    wtrans_kernel<<<(int)(((size_t)H * H + thr - 1) / thr), thr>>>(w2, p_w2t_hi, p_w2t_lo, H, H);
    wtrans_kernel<<<(int)(((size_t)2 * H * H + thr - 1) / thr), thr>>>(rw1, p_rw1t_hi, p_rw1t_lo, 2 * H, H);

    {
        size_t total4 = (size_t)NROWS * 3 * H / 4;
        concat_kernel<<<(int)((total4 + thr - 1) / thr), thr>>>(sfeat, pfeat, ofeat);
    }
    {
        cudaFuncSetAttribute(tgemm_kernel<true, false, true>,
                             cudaFuncAttributeMaxDynamicSharedMemorySize, TG_SMEM);
        dim3 grid(H / 128, NROWS / 128);
        tgemm_kernel<true, false, true><<<grid, 256, TG_SMEM>>>(
            p_vcat_hi, p_vcat_lo, p_w1t_hi, p_w1t_lo, b1,
            p_h_hi, p_h_lo, nullptr, 3 * H, H);
    }
    {
        cudaFuncSetAttribute(tgemm_kernel<false, true, true>,
                             cudaFuncAttributeMaxDynamicSharedMemorySize, TG_SMEM);
        dim3 grid(H / 128, NROWS / 128);
        tgemm_kernel<false, true, true><<<grid, 256, TG_SMEM>>>(
            p_h_hi, p_h_lo, p_w2t_hi, p_w2t_lo, b2,
            nullptr, nullptr, p_vf, H, H);
    }
    {
        cudaFuncSetAttribute(attn_kernel, cudaFuncAttributeMaxDynamicSharedMemorySize, A_SMEM);
        attn_kernel<<<NROWS, 256, A_SMEM>>>(p_vf, rel, scats, ocats, p_rf_hi, p_rf_lo);
    }
    {
        dim3 grid(H / 128, NROWS / 128);
        tgemm_kernel<false, true, true><<<grid, 256, TG_SMEM>>>(
            p_rf_hi, p_rf_lo, p_rw1t_hi, p_rw1t_lo, rb1,
            nullptr, nullptr, p_h2, 2 * H, H);
    }
    {
        dim3 grid(1, NROWS / 128);
        sgemm_kernel<false><<<grid, 256>>>(p_h2, rw2, rb2, out, NROWS, H, PP);
    }
}

// round 11
// speedup vs baseline: 1.0296x; 1.0296x over previous
#include <cuda_runtime.h>
#include <cuda_bf16.h>
#include <math.h>
#include <stdint.h>
#include <string.h>

#define NROWS 8192
#define H 512
#define CC 100
#define RR 69
#define PP 69
#define EPSV 1e-8f

typedef unsigned long long ull;

// ---------------- scratch (device globals, no runtime alloc) ----------------
__device__ __nv_bfloat16 g_vcat_hi[(size_t)NROWS * 3 * H];
__device__ __nv_bfloat16 g_vcat_lo[(size_t)NROWS * 3 * H];
__device__ __nv_bfloat16 g_h_hi[(size_t)NROWS * H];
__device__ __nv_bfloat16 g_h_lo[(size_t)NROWS * H];
__device__ float         g_vf[(size_t)NROWS * H];
__device__ __nv_bfloat16 g_rf_hi[(size_t)NROWS * 2 * H];
__device__ __nv_bfloat16 g_rf_lo[(size_t)NROWS * 2 * H];
__device__ float         g_h2[(size_t)NROWS * H];
__device__ __nv_bfloat16 g_w1t_hi[(size_t)H * 3 * H];
__device__ __nv_bfloat16 g_w1t_lo[(size_t)H * 3 * H];
__device__ __nv_bfloat16 g_w2t_hi[(size_t)H * H];
__device__ __nv_bfloat16 g_w2t_lo[(size_t)H * H];
__device__ __nv_bfloat16 g_rw1t_hi[(size_t)H * 2 * H];
__device__ __nv_bfloat16 g_rw1t_lo[(size_t)H * 2 * H];

// ---------------- helpers ----------------
__device__ __forceinline__ void split_bf16(float v, __nv_bfloat16& hi, __nv_bfloat16& lo) {
    hi = __float2bfloat16(v);
    lo = __float2bfloat16(v - __bfloat162float(hi));
}
__device__ __forceinline__ uint16_t bf_bits(__nv_bfloat16 h) {
    uint16_t b; memcpy(&b, &h, 2); return b;
}
__device__ __forceinline__ uint32_t smem_u32(const void* p) {
    return (uint32_t)__cvta_generic_to_shared(p);
}
__device__ __forceinline__ void cp_async16(uint32_t smem_dst, const void* gmem_src) {
    asm volatile("cp.async.cg.shared.global [%0], [%1], 16;" :: "r"(smem_dst), "l"(gmem_src) : "memory");
}
__device__ __forceinline__ void cp_commit() {
    asm volatile("cp.async.commit_group;" ::: "memory");
}
#define CP_WAIT(n) asm volatile("cp.async.wait_group %0;" :: "n"(n) : "memory")

__device__ __forceinline__ void mma16816(float* d, const uint32_t* a, const uint32_t* b) {
    asm volatile(
        "mma.sync.aligned.m16n8k16.row.col.f32.bf16.bf16.f32 "
        "{%0,%1,%2,%3},{%4,%5,%6,%7},{%8,%9},{%0,%1,%2,%3};"
        : "+f"(d[0]), "+f"(d[1]), "+f"(d[2]), "+f"(d[3])
        : "r"(a[0]), "r"(a[1]), "r"(a[2]), "r"(a[3]), "r"(b[0]), "r"(b[1]));
}
__device__ __forceinline__ void ldsm4(uint32_t& r0, uint32_t& r1, uint32_t& r2, uint32_t& r3,
                                      uint32_t addr) {
    asm volatile("ldmatrix.sync.aligned.m8n8.x4.shared.b16 {%0,%1,%2,%3}, [%4];"
        : "=r"(r0), "=r"(r1), "=r"(r2), "=r"(r3) : "r"(addr));
}

// ---------------- concat -> bf16 hi/lo ----------------
__global__ void concat_kernel(const float* __restrict__ s,
                              const float* __restrict__ p,
                              const float* __restrict__ o) {
    size_t idx = (size_t)blockIdx.x * blockDim.x + threadIdx.x;
    size_t total = (size_t)NROWS * 3 * H / 4;
    if (idx >= total) return;
    size_t row = idx / (3 * H / 4);
    size_t col4 = idx % (3 * H / 4);
    const float4* src;
    size_t within;
    if (col4 < H / 4)            { src = (const float4*)s; within = col4; }
    else if (col4 < 2 * (H / 4)) { src = (const float4*)p; within = col4 - H / 4; }
    else                         { src = (const float4*)o; within = col4 - 2 * (H / 4); }
    float4 v = src[row * (H / 4) + within];
    __nv_bfloat16 h0, l0, h1, l1, h2v, l2, h3, l3;
    split_bf16(v.x, h0, l0); split_bf16(v.y, h1, l1);
    split_bf16(v.z, h2v, l2); split_bf16(v.w, h3, l3);
    uint32_t* dh = (uint32_t*)(g_vcat_hi + idx * 4);
    uint32_t* dl = (uint32_t*)(g_vcat_lo + idx * 4);
    dh[0] = (uint32_t)bf_bits(h0) | ((uint32_t)bf_bits(h1) << 16);
    dh[1] = (uint32_t)bf_bits(h2v) | ((uint32_t)bf_bits(h3) << 16);
    dl[0] = (uint32_t)bf_bits(l0) | ((uint32_t)bf_bits(l1) << 16);
    dl[1] = (uint32_t)bf_bits(l2) | ((uint32_t)bf_bits(l3) << 16);
}

// ---------------- weight transpose + split ----------------
__global__ void wtrans_kernel(const float* __restrict__ W,
                              __nv_bfloat16* __restrict__ Thi,
                              __nv_bfloat16* __restrict__ Tlo,
                              int K, int N) {
    size_t idx = (size_t)blockIdx.x * blockDim.x + threadIdx.x;
    size_t total = (size_t)K * N;
    if (idx >= total) return;
    int n = (int)(idx / K);
    int k = (int)(idx % K);
    float v = W[(size_t)k * N + n];
    __nv_bfloat16 hi, lo;
    split_bf16(v, hi, lo);
    Thi[idx] = hi; Tlo[idx] = lo;
}

// ---------------- mma.sync bf16x3 GEMM, 3-stage cp.async + pipelined ldmatrix ----------------
#define TG_LDS 72
#define TG_STAGES 3
#define TG_STAGE_ELEMS (128 * TG_LDS)
#define TG_SMEM (2 * TG_STAGES * TG_STAGE_ELEMS * 2)   // 110592 B
#define TG_ROWB (TG_LDS * 2)                           // 144 B row stride

template<bool WB16, bool WF32, bool RELU>
__global__ __launch_bounds__(256, 2)
void tgemm_kernel(const __nv_bfloat16* __restrict__ Ahi, const __nv_bfloat16* __restrict__ Alo,
                  const __nv_bfloat16* __restrict__ Bhi, const __nv_bfloat16* __restrict__ Blo,
                  const float* __restrict__ bias,
                  __nv_bfloat16* __restrict__ Chi, __nv_bfloat16* __restrict__ Clo,
                  float* __restrict__ Cf32,
                  int K, int Ntot) {
    extern __shared__ __align__(16) __nv_bfloat16 smem[];

    const int tid = threadIdx.x;
    const int wid = tid >> 5;
    const int lane = tid & 31;
    const int g = lane >> 2;
    const int t = lane & 3;
    const int wm = wid & 3;
    const int wn = wid >> 2;
    const int bm = blockIdx.y * 128;
    const int bn = blockIdx.x * 128;

    const int per = K >> 6;
    const int C = 3 * per;

    // ldmatrix per-lane byte offsets (verified in R7: rel_err bit-identical)
    const uint32_t aoff = (uint32_t)((wm * 32 + (lane & 15)) * TG_ROWB + ((lane >> 4) * 8) * 2);
    const uint32_t boff = (uint32_t)((wn * 64 + ((lane >> 3) >> 1) * 8 + (lane & 7)) * TG_ROWB
                                     + (((lane >> 3) & 1) * 8) * 2);

    float acc[2][8][4];
#pragma unroll
    for (int i = 0; i < 2; i++)
#pragma unroll
        for (int j = 0; j < 8; j++)
#pragma unroll
            for (int q = 0; q < 4; q++) acc[i][j][q] = 0.f;

    auto load_chunk = [&](int c, int s) {
        int p = c / per;
        int kc = (c - p * per) << 6;
        const __nv_bfloat16* As = (p == 1) ? Alo : Ahi;
        const __nv_bfloat16* Bs = (p == 2) ? Blo : Bhi;
        uint32_t abase = smem_u32(smem + s * TG_STAGE_ELEMS);
        uint32_t bbase = smem_u32(smem + (TG_STAGES + s) * TG_STAGE_ELEMS);
#pragma unroll
        for (int i = 0; i < 4; i++) {
            int seg = tid + i * 256;
            int row = seg >> 3, sg = seg & 7;
            cp_async16(abase + (row * TG_LDS + sg * 8) * 2,
                       As + (size_t)(bm + row) * K + kc + sg * 8);
        }
#pragma unroll
        for (int i = 0; i < 4; i++) {
            int seg = tid + i * 256;
            int row = seg >> 3, sg = seg & 7;
            cp_async16(bbase + (row * TG_LDS + sg * 8) * 2,
                       Bs + (size_t)(bn + row) * K + kc + sg * 8);
        }
        cp_commit();
    };

    load_chunk(0, 0);
    load_chunk(1, 1);
    load_chunk(2, 2);

    for (int c = 0; c < C; c++) {
        const int s = c % TG_STAGES;
        CP_WAIT(2);                 // commits at entry = 3 + c
        __syncthreads();

        const uint32_t abase = smem_u32(smem + s * TG_STAGE_ELEMS) + aoff;
        const uint32_t bbase = smem_u32(smem + (TG_STAGES + s) * TG_STAGE_ELEMS) + boff;

        // double-buffered fragments: LDSM for ks+1 issued before HMMAs of ks
        uint32_t af[2][2][4];       // [buf][mt][reg]
        uint32_t bf[2][4][4];       // [buf][ntp][reg]

        // preload ks=0 into buf 0
        ldsm4(af[0][0][0], af[0][0][1], af[0][0][2], af[0][0][3], abase);
        ldsm4(af[0][1][0], af[0][1][1], af[0][1][2], af[0][1][3], abase + 16 * TG_ROWB);
#pragma unroll
        for (int ntp = 0; ntp < 4; ntp++)
            ldsm4(bf[0][ntp][0], bf[0][ntp][1], bf[0][ntp][2], bf[0][ntp][3],
                  bbase + ntp * 16 * TG_ROWB);

#pragma unroll
        for (int ks = 0; ks < 4; ks++) {
            const int cur = ks & 1;
            const int nxt = cur ^ 1;
            if (ks < 3) {
                const uint32_t k2 = (ks + 1) * 32;
                ldsm4(af[nxt][0][0], af[nxt][0][1], af[nxt][0][2], af[nxt][0][3], abase + k2);
                ldsm4(af[nxt][1][0], af[nxt][1][1], af[nxt][1][2], af[nxt][1][3],
                      abase + 16 * TG_ROWB + k2);
#pragma unroll
                for (int ntp = 0; ntp < 4; ntp++)
                    ldsm4(bf[nxt][ntp][0], bf[nxt][ntp][1], bf[nxt][ntp][2], bf[nxt][ntp][3],
                          bbase + ntp * 16 * TG_ROWB + k2);
            }
#pragma unroll
            for (int ntp = 0; ntp < 4; ntp++) {
                mma16816(acc[0][2 * ntp],     af[cur][0], bf[cur][ntp]);
                mma16816(acc[1][2 * ntp],     af[cur][1], bf[cur][ntp]);
                mma16816(acc[0][2 * ntp + 1], af[cur][0], bf[cur][ntp] + 2);
                mma16816(acc[1][2 * ntp + 1], af[cur][1], bf[cur][ntp] + 2);
            }
        }
        __syncthreads();
        if (c + 3 < C) load_chunk(c + 3, s);
        else cp_commit();
    }

    // epilogue
#pragma unroll
    for (int mt = 0; mt < 2; mt++) {
        int row0 = bm + wm * 32 + mt * 16 + g;
        int row1 = row0 + 8;
#pragma unroll
        for (int nt = 0; nt < 8; nt++) {
            int col = bn + wn * 64 + nt * 8 + 2 * t;
            float2 bv = __ldg((const float2*)(bias + col));
            float v0 = acc[mt][nt][0] + bv.x;
            float v1 = acc[mt][nt][1] + bv.y;
            float v2 = acc[mt][nt][2] + bv.x;
            float v3 = acc[mt][nt][3] + bv.y;
            if (RELU) {
                v0 = fmaxf(v0, 0.f); v1 = fmaxf(v1, 0.f);
                v2 = fmaxf(v2, 0.f); v3 = fmaxf(v3, 0.f);
            }
            if (WF32) {
                *(float2*)(Cf32 + (size_t)row0 * Ntot + col) = make_float2(v0, v1);
                *(float2*)(Cf32 + (size_t)row1 * Ntot + col) = make_float2(v2, v3);
            }
            if (WB16) {
                __nv_bfloat16 h0, l0, h1, l1, h2v, l2, h3, l3;
                split_bf16(v0, h0, l0); split_bf16(v1, h1, l1);
                split_bf16(v2, h2v, l2); split_bf16(v3, h3, l3);
                *(uint32_t*)(Chi + (size_t)row0 * Ntot + col) =
                    (uint32_t)bf_bits(h0) | ((uint32_t)bf_bits(h1) << 16);
                *(uint32_t*)(Chi + (size_t)row1 * Ntot + col) =
                    (uint32_t)bf_bits(h2v) | ((uint32_t)bf_bits(h3) << 16);
                *(uint32_t*)(Clo + (size_t)row0 * Ntot + col) =
                    (uint32_t)bf_bits(l0) | ((uint32_t)bf_bits(l1) << 16);
                *(uint32_t*)(Clo + (size_t)row1 * Ntot + col) =
                    (uint32_t)bf_bits(l2) | ((uint32_t)bf_bits(l3) << 16);
            }
        }
    }
}

// ---------------- FFMA2 SGEMM (final N=69 GEMM) ----------------
__device__ __forceinline__ ull pack2(float lo, float hi) {
    ull r; asm("mov.b64 %0, {%1, %2};" : "=l"(r) : "f"(lo), "f"(hi)); return r;
}
__device__ __forceinline__ void unpack2(ull v, float& lo, float& hi) {
    asm("mov.b64 {%0, %1}, %2;" : "=f"(lo), "=f"(hi) : "l"(v));
}
__device__ __forceinline__ void fma2(ull& d, ull a, ull b) {
    asm("fma.rn.f32x2 %0, %1, %2, %3;" : "=l"(d) : "l"(a), "l"(b), "l"(d));
}

template<bool RELU>
__global__ __launch_bounds__(256)
void sgemm_kernel(const float* __restrict__ A, const float* __restrict__ B,
                  const float* __restrict__ bias, float* __restrict__ C,
                  int M, int Kd, int Nd) {
    __shared__ float As[8][132];
    __shared__ float Bs[8][128];

    const int bm = blockIdx.y * 128;
    const int bn = blockIdx.x * 128;
    const int tid = threadIdx.x;
    const int arow = tid >> 1;
    const int acol = (tid & 1) * 4;
    const int brow = tid >> 5;
    const int bcol = (tid & 31) * 4;
    const int tx = tid & 15;
    const int ty = tid >> 4;

    ull acc2[4][8];
#pragma unroll
    for (int i = 0; i < 4; i++)
#pragma unroll
        for (int j = 0; j < 8; j++) acc2[i][j] = 0ull;

    const bool full_n = (bn + 128 <= Nd);

    for (int k0 = 0; k0 < Kd; k0 += 8) {
        float4 a4 = *(const float4*)(A + (size_t)(bm + arow) * Kd + k0 + acol);
        As[acol + 0][arow] = a4.x;
        As[acol + 1][arow] = a4.y;
        As[acol + 2][arow] = a4.z;
        As[acol + 3][arow] = a4.w;
        if (full_n) {
            *(float4*)&Bs[brow][bcol] =
                *(const float4*)(B + (size_t)(k0 + brow) * Nd + bn + bcol);
        } else {
#pragma unroll
            for (int c = 0; c < 4; c++) {
                int col = bn + bcol + c;
                Bs[brow][bcol + c] = (col < Nd) ? B[(size_t)(k0 + brow) * Nd + col] : 0.f;
            }
        }
        __syncthreads();
#pragma unroll
        for (int k = 0; k < 8; k++) {
            ulonglong2 av0 = *(const ulonglong2*)&As[k][ty * 8];
            ulonglong2 av1 = *(const ulonglong2*)&As[k][ty * 8 + 4];
            ull a2[4] = {av0.x, av0.y, av1.x, av1.y};
            float4 blo = *(const float4*)&Bs[k][tx * 8];
            float4 bhi = *(const float4*)&Bs[k][tx * 8 + 4];
            ull b2[8];
            b2[0] = pack2(blo.x, blo.x); b2[1] = pack2(blo.y, blo.y);
            b2[2] = pack2(blo.z, blo.z); b2[3] = pack2(blo.w, blo.w);
            b2[4] = pack2(bhi.x, bhi.x); b2[5] = pack2(bhi.y, bhi.y);
            b2[6] = pack2(bhi.z, bhi.z); b2[7] = pack2(bhi.w, bhi.w);
#pragma unroll
            for (int i = 0; i < 4; i++)
#pragma unroll
                for (int j = 0; j < 8; j++)
                    fma2(acc2[i][j], a2[i], b2[j]);
        }
        __syncthreads();
    }
#pragma unroll
    for (int i = 0; i < 4; i++) {
        int row_lo = bm + ty * 8 + 2 * i;
        float* c0 = C + (size_t)row_lo * Nd;
        float* c1 = C + (size_t)(row_lo + 1) * Nd;
#pragma unroll
        for (int j = 0; j < 8; j++) {
            int col = bn + tx * 8 + j;
            if (col < Nd) {
                float lo, hi;
                unpack2(acc2[i][j], lo, hi);
                float bv = bias[col];
                lo += bv; hi += bv;
                if (RELU) { lo = fmaxf(lo, 0.f); hi = fmaxf(hi, 0.f); }
                c0[col] = lo;
                c1[col] = hi;
            }
        }
    }
}

// ---------------- streaming online-softmax attention ----------------
#define ACH 8
#define ASTAGES 3
#define A_SMEM ((ASTAGES * ACH * H + H + 4 * ACH + 8) * 4)

__global__ __launch_bounds__(256)
void attn_kernel(const float* __restrict__ vf,
                 const float* __restrict__ rel_base,
                 const int* __restrict__ scats,
                 const int* __restrict__ ocats,
                 __nv_bfloat16* __restrict__ rf_hi,
                 __nv_bfloat16* __restrict__ rf_lo) {
    extern __shared__ float sm[];
    float* ring  = sm;
    float* svf   = ring + ASTAGES * ACH * H;
    float* sdot  = svf + H;
    float* ssq   = sdot + ACH;
    float* sw    = ssq + ACH;
    float* sred  = sw + ACH;
    float* sstat = sred + 8;

    const int n = blockIdx.x;
    const int tid = threadIdx.x;
    const int lane = tid & 31;
    const int warp = tid >> 5;

    const int s = scats[n];
    const int o = ocats[n];
    const float* relp = rel_base + (((size_t)s * RR) * CC + o) * H;

    auto load_chunk = [&](int tc) {
        float* dst = ring + (tc % ASTAGES) * (ACH * H);
#pragma unroll
        for (int i = 0; i < 4; i++) {
            int idx = tid + i * 256;
            int j = idx >> 7;
            int col4 = idx & 127;
            int r = tc * ACH + j;
            if (r < RR)
                cp_async16(smem_u32(dst + j * H + col4 * 4),
                           relp + (size_t)r * CC * H + col4 * 4);
        }
        cp_commit();
    };

    if (tid < 128)
        ((float4*)svf)[tid] = __ldg(&((const float4*)(vf + (size_t)n * H))[tid]);

    load_chunk(0);
    load_chunk(1);
    load_chunk(2);

    __syncthreads();
    {
        float v0 = svf[tid], v1 = svf[tid + 256];
        float part = v0 * v0 + v1 * v1;
#pragma unroll
        for (int off = 16; off > 0; off >>= 1)
            part += __shfl_xor_sync(0xffffffffu, part, off);
        if (lane == 0) sred[warp] = part;
    }

    const int chunks = (RR + ACH - 1) / ACH;
    float acc0 = 0.f, acc1 = 0.f;
    float m_run = -1e30f, s_run = 0.f, vn = 0.f;

    for (int tc = 0; tc < chunks; tc++) {
        CP_WAIT(2);
        __syncthreads();

        {
            const float4* cb4 = (const float4*)(ring + (tc % ASTAGES) * (ACH * H) + warp * H);
            const float4* vf4s = (const float4*)svf;
            float dot = 0.f, sq = 0.f;
#pragma unroll
            for (int i = 0; i < 4; i++) {
                float4 x = cb4[lane + 32 * i];
                float4 v = vf4s[lane + 32 * i];
                dot += x.x * v.x + x.y * v.y + x.z * v.z + x.w * v.w;
                sq  += x.x * x.x + x.y * x.y + x.z * x.z + x.w * x.w;
            }
#pragma unroll
            for (int off = 16; off > 0; off >>= 1) {
                dot += __shfl_down_sync(0xffffffffu, dot, off);
                sq  += __shfl_down_sync(0xffffffffu, sq, off);
            }
            if (lane == 0) { sdot[warp] = dot; ssq[warp] = sq; }
        }
        __syncthreads();

        if (warp == 0) {
            if (tc == 0) {
                float vsq = (lane < 8) ? sred[lane] : 0.f;
#pragma unroll
                for (int off = 4; off > 0; off >>= 1)
                    vsq += __shfl_xor_sync(0xffffffffu, vsq, off);
                vsq = __shfl_sync(0xffffffffu, vsq, 0);
                vn = sqrtf(vsq);
            }
            int r = tc * ACH + lane;
            float c = -1e30f;
            if (lane < ACH && r < RR)
                c = sdot[lane] / fmaxf(vn * sqrtf(ssq[lane]), EPSV);
            float mc = c;
#pragma unroll
            for (int off = 16; off > 0; off >>= 1)
                mc = fmaxf(mc, __shfl_xor_sync(0xffffffffu, mc, off));
            float m_new = fmaxf(m_run, mc);
            float w = (lane < ACH) ? __expf(c - m_new) : 0.f;
            float wsum = w;
#pragma unroll
            for (int off = 16; off > 0; off >>= 1)
                wsum += __shfl_xor_sync(0xffffffffu, wsum, off);
            float scale = __expf(m_run - m_new);
            s_run = s_run * scale + wsum;
            m_run = m_new;
            if (lane < ACH) sw[lane] = w;
            if (lane == 0) sstat[0] = scale;
            if (lane == 0 && tc == chunks - 1) sstat[1] = s_run;
        }
        __syncthreads();

        {
            float scale = sstat[0];
            acc0 *= scale; acc1 *= scale;
            const float* cb = ring + (tc % ASTAGES) * (ACH * H);
#pragma unroll
            for (int r = 0; r < ACH; r++) {
                float wr = sw[r];
                acc0 = fmaf(wr, cb[r * H + tid], acc0);
                acc1 = fmaf(wr, cb[r * H + tid + 256], acc1);
            }
        }
        __syncthreads();

        if (tc + 3 < chunks) load_chunk(tc + 3);
        else cp_commit();
    }

    float inv = 1.f / sstat[1];
    float att0 = acc0 * inv, att1 = acc1 * inv;
    float vv0 = svf[tid], vv1 = svf[tid + 256];

    __nv_bfloat16 h, l;
    size_t base = (size_t)n * 2 * H;
    split_bf16(vv0, h, l);  rf_hi[base + tid] = h;          rf_lo[base + tid] = l;
    split_bf16(vv1, h, l);  rf_hi[base + tid + 256] = h;    rf_lo[base + tid + 256] = l;
    split_bf16(att0, h, l); rf_hi[base + H + tid] = h;      rf_lo[base + H + tid] = l;
    split_bf16(att1, h, l); rf_hi[base + H + tid + 256] = h; rf_lo[base + H + tid + 256] = l;
}

// ---------------- launch ----------------
extern "C" void kernel_launch(void* const* d_in, const int* in_sizes, int n_in,
                              void* d_out, int out_size) {
    if (n_in < 14) return;
    const float* sfeat = (const float*)d_in[0];
    const float* pfeat = (const float*)d_in[1];
    const float* ofeat = (const float*)d_in[2];
    const float* rel   = (const float*)d_in[3];
    const float* w1    = (const float*)d_in[4];
    const float* b1    = (const float*)d_in[5];
    const float* w2    = (const float*)d_in[6];
    const float* b2    = (const float*)d_in[7];
    const float* rw1   = (const float*)d_in[8];
    const float* rb1   = (const float*)d_in[9];
    const float* rw2   = (const float*)d_in[10];
    const float* rb2   = (const float*)d_in[11];
    const int*   scats = (const int*)d_in[12];
    const int*   ocats = (const int*)d_in[13];
    float* out = (float*)d_out;

    __nv_bfloat16 *p_vcat_hi, *p_vcat_lo, *p_h_hi, *p_h_lo;
    __nv_bfloat16 *p_rf_hi, *p_rf_lo;
    __nv_bfloat16 *p_w1t_hi, *p_w1t_lo, *p_w2t_hi, *p_w2t_lo, *p_rw1t_hi, *p_rw1t_lo;
    float *p_vf, *p_h2;
    cudaGetSymbolAddress((void**)&p_vcat_hi, g_vcat_hi);
    cudaGetSymbolAddress((void**)&p_vcat_lo, g_vcat_lo);
    cudaGetSymbolAddress((void**)&p_h_hi, g_h_hi);
    cudaGetSymbolAddress((void**)&p_h_lo, g_h_lo);
    cudaGetSymbolAddress((void**)&p_vf, g_vf);
    cudaGetSymbolAddress((void**)&p_rf_hi, g_rf_hi);
    cudaGetSymbolAddress((void**)&p_rf_lo, g_rf_lo);
    cudaGetSymbolAddress((void**)&p_h2, g_h2);
    cudaGetSymbolAddress((void**)&p_w1t_hi, g_w1t_hi);
    cudaGetSymbolAddress((void**)&p_w1t_lo, g_w1t_lo);
    cudaGetSymbolAddress((void**)&p_w2t_hi, g_w2t_hi);
    cudaGetSymbolAddress((void**)&p_w2t_lo, g_w2t_lo);
    cudaGetSymbolAddress((void**)&p_rw1t_hi, g_rw1t_hi);
    cudaGetSymbolAddress((void**)&p_rw1t_lo, g_rw1t_lo);

    const int thr = 256;

    wtrans_kernel<<<(int)(((size_t)3 * H * H + thr - 1) / thr), thr>>>(w1, p_w1t_hi, p_w1t_lo, 3 * H, H);
    wtrans_kernel<<<(int)(((size_t)H * H + thr - 1) / thr), thr>>>(w2, p_w2t_hi, p_w2t_lo, H, H);
    wtrans_kernel<<<(int)(((size_t)2 * H * H + thr - 1) / thr), thr>>>(rw1, p_rw1t_hi, p_rw1t_lo, 2 * H, H);

    {
        size_t total4 = (size_t)NROWS * 3 * H / 4;
        concat_kernel<<<(int)((total4 + thr - 1) / thr), thr>>>(sfeat, pfeat, ofeat);
    }
    {
        cudaFuncSetAttribute(tgemm_kernel<true, false, true>,
                             cudaFuncAttributeMaxDynamicSharedMemorySize, TG_SMEM);
        dim3 grid(H / 128, NROWS / 128);
        tgemm_kernel<true, false, true><<<grid, 256, TG_SMEM>>>(
            p_vcat_hi, p_vcat_lo, p_w1t_hi, p_w1t_lo, b1,
            p_h_hi, p_h_lo, nullptr, 3 * H, H);
    }
    {
        cudaFuncSetAttribute(tgemm_kernel<false, true, true>,
                             cudaFuncAttributeMaxDynamicSharedMemorySize, TG_SMEM);
        dim3 grid(H / 128, NROWS / 128);
        tgemm_kernel<false, true, true><<<grid, 256, TG_SMEM>>>(
            p_h_hi, p_h_lo, p_w2t_hi, p_w2t_lo, b2,
            nullptr, nullptr, p_vf, H, H);
    }
    {
        cudaFuncSetAttribute(attn_kernel, cudaFuncAttributeMaxDynamicSharedMemorySize, A_SMEM);
        attn_kernel<<<NROWS, 256, A_SMEM>>>(p_vf, rel, scats, ocats, p_rf_hi, p_rf_lo);
    }
    {
        dim3 grid(H / 128, NROWS / 128);
        tgemm_kernel<false, true, true><<<grid, 256, TG_SMEM>>>(
            p_rf_hi, p_rf_lo, p_rw1t_hi, p_rw1t_lo, rb1,
            nullptr, nullptr, p_h2, 2 * H, H);
    }
    {
        dim3 grid(1, NROWS / 128);
        sgemm_kernel<false><<<grid, 256>>>(p_h2, rw2, rb2, out, NROWS, H, PP);
    }
}

// round 12
// speedup vs baseline: 1.4568x; 1.4148x over previous
#include <cuda_runtime.h>
#include <cuda_fp16.h>
#include <math.h>
#include <stdint.h>
#include <string.h>

#define NROWS 8192
#define H 512
#define CC 100
#define RR 69
#define PP 69
#define EPSV 1e-8f

typedef unsigned long long ull;

// ---------------- scratch (device globals, no runtime alloc) ----------------
__device__ __half g_vcat[(size_t)NROWS * 3 * H];
__device__ __half g_h[(size_t)NROWS * H];
__device__ float  g_vf[(size_t)NROWS * H];
__device__ __half g_rf[(size_t)NROWS * 2 * H];
__device__ float  g_h2[(size_t)NROWS * H];
__device__ __half g_w1t[(size_t)H * 3 * H];
__device__ __half g_w2t[(size_t)H * H];
__device__ __half g_rw1t[(size_t)H * 2 * H];

// ---------------- helpers ----------------
__device__ __forceinline__ uint32_t pack_h2(float a, float b) {
    __half2 h = __floats2half2_rn(a, b);
    uint32_t r; memcpy(&r, &h, 4); return r;
}
__device__ __forceinline__ uint32_t smem_u32(const void* p) {
    return (uint32_t)__cvta_generic_to_shared(p);
}
__device__ __forceinline__ void cp_async16(uint32_t smem_dst, const void* gmem_src) {
    asm volatile("cp.async.cg.shared.global [%0], [%1], 16;" :: "r"(smem_dst), "l"(gmem_src) : "memory");
}
__device__ __forceinline__ void cp_commit() {
    asm volatile("cp.async.commit_group;" ::: "memory");
}
#define CP_WAIT(n) asm volatile("cp.async.wait_group %0;" :: "n"(n) : "memory")

__device__ __forceinline__ void mma16816(float* d, const uint32_t* a, const uint32_t* b) {
    asm volatile(
        "mma.sync.aligned.m16n8k16.row.col.f32.f16.f16.f32 "
        "{%0,%1,%2,%3},{%4,%5,%6,%7},{%8,%9},{%0,%1,%2,%3};"
        : "+f"(d[0]), "+f"(d[1]), "+f"(d[2]), "+f"(d[3])
        : "r"(a[0]), "r"(a[1]), "r"(a[2]), "r"(a[3]), "r"(b[0]), "r"(b[1]));
}
__device__ __forceinline__ void ldsm4(uint32_t& r0, uint32_t& r1, uint32_t& r2, uint32_t& r3,
                                      uint32_t addr) {
    asm volatile("ldmatrix.sync.aligned.m8n8.x4.shared.b16 {%0,%1,%2,%3}, [%4];"
        : "=r"(r0), "=r"(r1), "=r"(r2), "=r"(r3) : "r"(addr));
}

// ---------------- concat -> fp16 ----------------
__global__ void concat_kernel(const float* __restrict__ s,
                              const float* __restrict__ p,
                              const float* __restrict__ o) {
    size_t idx = (size_t)blockIdx.x * blockDim.x + threadIdx.x;   // float4 index
    size_t total = (size_t)NROWS * 3 * H / 4;
    if (idx >= total) return;
    size_t row = idx / (3 * H / 4);
    size_t col4 = idx % (3 * H / 4);
    const float4* src;
    size_t within;
    if (col4 < H / 4)            { src = (const float4*)s; within = col4; }
    else if (col4 < 2 * (H / 4)) { src = (const float4*)p; within = col4 - H / 4; }
    else                         { src = (const float4*)o; within = col4 - 2 * (H / 4); }
    float4 v = src[row * (H / 4) + within];
    uint32_t* d = (uint32_t*)(g_vcat + idx * 4);
    d[0] = pack_h2(v.x, v.y);
    d[1] = pack_h2(v.z, v.w);
}

// ---------------- weight transpose: W[K,N] f32 -> T[N,K] fp16 ----------------
__global__ void wtrans_kernel(const float* __restrict__ W,
                              __half* __restrict__ T,
                              int K, int N) {
    size_t idx = (size_t)blockIdx.x * blockDim.x + threadIdx.x;
    size_t total = (size_t)K * N;
    if (idx >= total) return;
    int n = (int)(idx / K);
    int k = (int)(idx % K);
    T[idx] = __float2half_rn(W[(size_t)k * N + n]);
}

// ---------------- fp16 single-pass mma.sync GEMM, 3-stage cp.async + pipelined ldmatrix ----------------
#define TG_LDS 72
#define TG_STAGES 3
#define TG_STAGE_ELEMS (128 * TG_LDS)
#define TG_SMEM (2 * TG_STAGES * TG_STAGE_ELEMS * 2)   // 110592 B
#define TG_ROWB (TG_LDS * 2)                           // 144 B row stride

template<bool WH16, bool WF32, bool RELU>
__global__ __launch_bounds__(256, 2)
void tgemm_kernel(const __half* __restrict__ A, const __half* __restrict__ B,
                  const float* __restrict__ bias,
                  __half* __restrict__ Ch, float* __restrict__ Cf32,
                  int K, int Ntot) {
    extern __shared__ __align__(16) __half smem[];

    const int tid = threadIdx.x;
    const int wid = tid >> 5;
    const int lane = tid & 31;
    const int g = lane >> 2;
    const int t = lane & 3;
    const int wm = wid & 3;
    const int wn = wid >> 2;
    const int bm = blockIdx.y * 128;
    const int bn = blockIdx.x * 128;

    const int C = K >> 6;          // single pass: chunks of 64

    const uint32_t aoff = (uint32_t)((wm * 32 + (lane & 15)) * TG_ROWB + ((lane >> 4) * 8) * 2);
    const uint32_t boff = (uint32_t)((wn * 64 + ((lane >> 3) >> 1) * 8 + (lane & 7)) * TG_ROWB
                                     + (((lane >> 3) & 1) * 8) * 2);

    float acc[2][8][4];
#pragma unroll
    for (int i = 0; i < 2; i++)
#pragma unroll
        for (int j = 0; j < 8; j++)
#pragma unroll
            for (int q = 0; q < 4; q++) acc[i][j][q] = 0.f;

    auto load_chunk = [&](int c, int s) {
        int kc = c << 6;
        uint32_t abase = smem_u32(smem + s * TG_STAGE_ELEMS);
        uint32_t bbase = smem_u32(smem + (TG_STAGES + s) * TG_STAGE_ELEMS);
#pragma unroll
        for (int i = 0; i < 4; i++) {
            int seg = tid + i * 256;
            int row = seg >> 3, sg = seg & 7;
            cp_async16(abase + (row * TG_LDS + sg * 8) * 2,
                       A + (size_t)(bm + row) * K + kc + sg * 8);
        }
#pragma unroll
        for (int i = 0; i < 4; i++) {
            int seg = tid + i * 256;
            int row = seg >> 3, sg = seg & 7;
            cp_async16(bbase + (row * TG_LDS + sg * 8) * 2,
                       B + (size_t)(bn + row) * K + kc + sg * 8);
        }
        cp_commit();
    };

    load_chunk(0, 0);
    load_chunk(1, 1);
    load_chunk(2, 2);

    for (int c = 0; c < C; c++) {
        const int s = c % TG_STAGES;
        CP_WAIT(2);
        __syncthreads();

        const uint32_t abase = smem_u32(smem + s * TG_STAGE_ELEMS) + aoff;
        const uint32_t bbase = smem_u32(smem + (TG_STAGES + s) * TG_STAGE_ELEMS) + boff;

        uint32_t af[2][2][4];
        uint32_t bf[2][4][4];

        ldsm4(af[0][0][0], af[0][0][1], af[0][0][2], af[0][0][3], abase);
        ldsm4(af[0][1][0], af[0][1][1], af[0][1][2], af[0][1][3], abase + 16 * TG_ROWB);
#pragma unroll
        for (int ntp = 0; ntp < 4; ntp++)
            ldsm4(bf[0][ntp][0], bf[0][ntp][1], bf[0][ntp][2], bf[0][ntp][3],
                  bbase + ntp * 16 * TG_ROWB);

#pragma unroll
        for (int ks = 0; ks < 4; ks++) {
            const int cur = ks & 1;
            const int nxt = cur ^ 1;
            if (ks < 3) {
                const uint32_t k2 = (ks + 1) * 32;
                ldsm4(af[nxt][0][0], af[nxt][0][1], af[nxt][0][2], af[nxt][0][3], abase + k2);
                ldsm4(af[nxt][1][0], af[nxt][1][1], af[nxt][1][2], af[nxt][1][3],
                      abase + 16 * TG_ROWB + k2);
#pragma unroll
                for (int ntp = 0; ntp < 4; ntp++)
                    ldsm4(bf[nxt][ntp][0], bf[nxt][ntp][1], bf[nxt][ntp][2], bf[nxt][ntp][3],
                          bbase + ntp * 16 * TG_ROWB + k2);
            }
#pragma unroll
            for (int ntp = 0; ntp < 4; ntp++) {
                mma16816(acc[0][2 * ntp],     af[cur][0], bf[cur][ntp]);
                mma16816(acc[1][2 * ntp],     af[cur][1], bf[cur][ntp]);
                mma16816(acc[0][2 * ntp + 1], af[cur][0], bf[cur][ntp] + 2);
                mma16816(acc[1][2 * ntp + 1], af[cur][1], bf[cur][ntp] + 2);
            }
        }
        __syncthreads();
        if (c + 3 < C) load_chunk(c + 3, s);
        else cp_commit();
    }

    // epilogue
#pragma unroll
    for (int mt = 0; mt < 2; mt++) {
        int row0 = bm + wm * 32 + mt * 16 + g;
        int row1 = row0 + 8;
#pragma unroll
        for (int nt = 0; nt < 8; nt++) {
            int col = bn + wn * 64 + nt * 8 + 2 * t;
            float2 bv = __ldg((const float2*)(bias + col));
            float v0 = acc[mt][nt][0] + bv.x;
            float v1 = acc[mt][nt][1] + bv.y;
            float v2 = acc[mt][nt][2] + bv.x;
            float v3 = acc[mt][nt][3] + bv.y;
            if (RELU) {
                v0 = fmaxf(v0, 0.f); v1 = fmaxf(v1, 0.f);
                v2 = fmaxf(v2, 0.f); v3 = fmaxf(v3, 0.f);
            }
            if (WF32) {
                *(float2*)(Cf32 + (size_t)row0 * Ntot + col) = make_float2(v0, v1);
                *(float2*)(Cf32 + (size_t)row1 * Ntot + col) = make_float2(v2, v3);
            }
            if (WH16) {
                *(uint32_t*)(Ch + (size_t)row0 * Ntot + col) = pack_h2(v0, v1);
                *(uint32_t*)(Ch + (size_t)row1 * Ntot + col) = pack_h2(v2, v3);
            }
        }
    }
}

// ---------------- FFMA2 SGEMM (final N=69 GEMM, fp32) ----------------
__device__ __forceinline__ ull pack2(float lo, float hi) {
    ull r; asm("mov.b64 %0, {%1, %2};" : "=l"(r) : "f"(lo), "f"(hi)); return r;
}
__device__ __forceinline__ void unpack2(ull v, float& lo, float& hi) {
    asm("mov.b64 {%0, %1}, %2;" : "=f"(lo), "=f"(hi) : "l"(v));
}
__device__ __forceinline__ void fma2(ull& d, ull a, ull b) {
    asm("fma.rn.f32x2 %0, %1, %2, %3;" : "=l"(d) : "l"(a), "l"(b), "l"(d));
}

template<bool RELU>
__global__ __launch_bounds__(256)
void sgemm_kernel(const float* __restrict__ A, const float* __restrict__ B,
                  const float* __restrict__ bias, float* __restrict__ C,
                  int M, int Kd, int Nd) {
    __shared__ float As[8][132];
    __shared__ float Bs[8][128];

    const int bm = blockIdx.y * 128;
    const int bn = blockIdx.x * 128;
    const int tid = threadIdx.x;
    const int arow = tid >> 1;
    const int acol = (tid & 1) * 4;
    const int brow = tid >> 5;
    const int bcol = (tid & 31) * 4;
    const int tx = tid & 15;
    const int ty = tid >> 4;

    ull acc2[4][8];
#pragma unroll
    for (int i = 0; i < 4; i++)
#pragma unroll
        for (int j = 0; j < 8; j++) acc2[i][j] = 0ull;

    const bool full_n = (bn + 128 <= Nd);

    for (int k0 = 0; k0 < Kd; k0 += 8) {
        float4 a4 = *(const float4*)(A + (size_t)(bm + arow) * Kd + k0 + acol);
        As[acol + 0][arow] = a4.x;
        As[acol + 1][arow] = a4.y;
        As[acol + 2][arow] = a4.z;
        As[acol + 3][arow] = a4.w;
        if (full_n) {
            *(float4*)&Bs[brow][bcol] =
                *(const float4*)(B + (size_t)(k0 + brow) * Nd + bn + bcol);
        } else {
#pragma unroll
            for (int c = 0; c < 4; c++) {
                int col = bn + bcol + c;
                Bs[brow][bcol + c] = (col < Nd) ? B[(size_t)(k0 + brow) * Nd + col] : 0.f;
            }
        }
        __syncthreads();
#pragma unroll
        for (int k = 0; k < 8; k++) {
            ulonglong2 av0 = *(const ulonglong2*)&As[k][ty * 8];
            ulonglong2 av1 = *(const ulonglong2*)&As[k][ty * 8 + 4];
            ull a2[4] = {av0.x, av0.y, av1.x, av1.y};
            float4 blo = *(const float4*)&Bs[k][tx * 8];
            float4 bhi = *(const float4*)&Bs[k][tx * 8 + 4];
            ull b2[8];
            b2[0] = pack2(blo.x, blo.x); b2[1] = pack2(blo.y, blo.y);
            b2[2] = pack2(blo.z, blo.z); b2[3] = pack2(blo.w, blo.w);
            b2[4] = pack2(bhi.x, bhi.x); b2[5] = pack2(bhi.y, bhi.y);
            b2[6] = pack2(bhi.z, bhi.z); b2[7] = pack2(bhi.w, bhi.w);
#pragma unroll
            for (int i = 0; i < 4; i++)
#pragma unroll
                for (int j = 0; j < 8; j++)
                    fma2(acc2[i][j], a2[i], b2[j]);
        }
        __syncthreads();
    }
#pragma unroll
    for (int i = 0; i < 4; i++) {
        int row_lo = bm + ty * 8 + 2 * i;
        float* c0 = C + (size_t)row_lo * Nd;
        float* c1 = C + (size_t)(row_lo + 1) * Nd;
#pragma unroll
        for (int j = 0; j < 8; j++) {
            int col = bn + tx * 8 + j;
            if (col < Nd) {
                float lo, hi;
                unpack2(acc2[i][j], lo, hi);
                float bv = bias[col];
                lo += bv; hi += bv;
                if (RELU) { lo = fmaxf(lo, 0.f); hi = fmaxf(hi, 0.f); }
                c0[col] = lo;
                c1[col] = hi;
            }
        }
    }
}

// ---------------- streaming online-softmax attention (writes rf fp16) ----------------
#define ACH 8
#define ASTAGES 3
#define A_SMEM ((ASTAGES * ACH * H + H + 4 * ACH + 8) * 4)

__global__ __launch_bounds__(256)
void attn_kernel(const float* __restrict__ vf,
                 const float* __restrict__ rel_base,
                 const int* __restrict__ scats,
                 const int* __restrict__ ocats,
                 __half* __restrict__ rf) {
    extern __shared__ float sm[];
    float* ring  = sm;
    float* svf   = ring + ASTAGES * ACH * H;
    float* sdot  = svf + H;
    float* ssq   = sdot + ACH;
    float* sw    = ssq + ACH;
    float* sred  = sw + ACH;
    float* sstat = sred + 8;

    const int n = blockIdx.x;
    const int tid = threadIdx.x;
    const int lane = tid & 31;
    const int warp = tid >> 5;

    const int s = scats[n];
    const int o = ocats[n];
    const float* relp = rel_base + (((size_t)s * RR) * CC + o) * H;

    auto load_chunk = [&](int tc) {
        float* dst = ring + (tc % ASTAGES) * (ACH * H);
#pragma unroll
        for (int i = 0; i < 4; i++) {
            int idx = tid + i * 256;
            int j = idx >> 7;
            int col4 = idx & 127;
            int r = tc * ACH + j;
            if (r < RR)
                cp_async16(smem_u32(dst + j * H + col4 * 4),
                           relp + (size_t)r * CC * H + col4 * 4);
        }
        cp_commit();
    };

    if (tid < 128)
        ((float4*)svf)[tid] = __ldg(&((const float4*)(vf + (size_t)n * H))[tid]);

    load_chunk(0);
    load_chunk(1);
    load_chunk(2);

    __syncthreads();
    {
        float v0 = svf[tid], v1 = svf[tid + 256];
        float part = v0 * v0 + v1 * v1;
#pragma unroll
        for (int off = 16; off > 0; off >>= 1)
            part += __shfl_xor_sync(0xffffffffu, part, off);
        if (lane == 0) sred[warp] = part;
    }

    const int chunks = (RR + ACH - 1) / ACH;
    float acc0 = 0.f, acc1 = 0.f;
    float m_run = -1e30f, s_run = 0.f, vn = 0.f;

    for (int tc = 0; tc < chunks; tc++) {
        CP_WAIT(2);
        __syncthreads();

        {
            const float4* cb4 = (const float4*)(ring + (tc % ASTAGES) * (ACH * H) + warp * H);
            const float4* vf4s = (const float4*)svf;
            float dot = 0.f, sq = 0.f;
#pragma unroll
            for (int i = 0; i < 4; i++) {
                float4 x = cb4[lane + 32 * i];
                float4 v = vf4s[lane + 32 * i];
                dot += x.x * v.x + x.y * v.y + x.z * v.z + x.w * v.w;
                sq  += x.x * x.x + x.y * x.y + x.z * x.z + x.w * x.w;
            }
#pragma unroll
            for (int off = 16; off > 0; off >>= 1) {
                dot += __shfl_down_sync(0xffffffffu, dot, off);
                sq  += __shfl_down_sync(0xffffffffu, sq, off);
            }
            if (lane == 0) { sdot[warp] = dot; ssq[warp] = sq; }
        }
        __syncthreads();

        if (warp == 0) {
            if (tc == 0) {
                float vsq = (lane < 8) ? sred[lane] : 0.f;
#pragma unroll
                for (int off = 4; off > 0; off >>= 1)
                    vsq += __shfl_xor_sync(0xffffffffu, vsq, off);
                vsq = __shfl_sync(0xffffffffu, vsq, 0);
                vn = sqrtf(vsq);
            }
            int r = tc * ACH + lane;
            float c = -1e30f;
            if (lane < ACH && r < RR)
                c = sdot[lane] / fmaxf(vn * sqrtf(ssq[lane]), EPSV);
            float mc = c;
#pragma unroll
            for (int off = 16; off > 0; off >>= 1)
                mc = fmaxf(mc, __shfl_xor_sync(0xffffffffu, mc, off));
            float m_new = fmaxf(m_run, mc);
            float w = (lane < ACH) ? __expf(c - m_new) : 0.f;
            float wsum = w;
#pragma unroll
            for (int off = 16; off > 0; off >>= 1)
                wsum += __shfl_xor_sync(0xffffffffu, wsum, off);
            float scale = __expf(m_run - m_new);
            s_run = s_run * scale + wsum;
            m_run = m_new;
            if (lane < ACH) sw[lane] = w;
            if (lane == 0) sstat[0] = scale;
            if (lane == 0 && tc == chunks - 1) sstat[1] = s_run;
        }
        __syncthreads();

        {
            float scale = sstat[0];
            acc0 *= scale; acc1 *= scale;
            const float* cb = ring + (tc % ASTAGES) * (ACH * H);
#pragma unroll
            for (int r = 0; r < ACH; r++) {
                float wr = sw[r];
                acc0 = fmaf(wr, cb[r * H + tid], acc0);
                acc1 = fmaf(wr, cb[r * H + tid + 256], acc1);
            }
        }
        __syncthreads();

        if (tc + 3 < chunks) load_chunk(tc + 3);
        else cp_commit();
    }

    float inv = 1.f / sstat[1];
    float att0 = acc0 * inv, att1 = acc1 * inv;
    float vv0 = svf[tid], vv1 = svf[tid + 256];

    size_t base = (size_t)n * 2 * H;
    rf[base + tid]           = __float2half_rn(vv0);
    rf[base + tid + 256]     = __float2half_rn(vv1);
    rf[base + H + tid]       = __float2half_rn(att0);
    rf[base + H + tid + 256] = __float2half_rn(att1);
}

// ---------------- launch ----------------
extern "C" void kernel_launch(void* const* d_in, const int* in_sizes, int n_in,
                              void* d_out, int out_size) {
    if (n_in < 14) return;
    const float* sfeat = (const float*)d_in[0];
    const float* pfeat = (const float*)d_in[1];
    const float* ofeat = (const float*)d_in[2];
    const float* rel   = (const float*)d_in[3];
    const float* w1    = (const float*)d_in[4];
    const float* b1    = (const float*)d_in[5];
    const float* w2    = (const float*)d_in[6];
    const float* b2    = (const float*)d_in[7];
    const float* rw1   = (const float*)d_in[8];
    const float* rb1   = (const float*)d_in[9];
    const float* rw2   = (const float*)d_in[10];
    const float* rb2   = (const float*)d_in[11];
    const int*   scats = (const int*)d_in[12];
    const int*   ocats = (const int*)d_in[13];
    float* out = (float*)d_out;

    __half *p_vcat, *p_h, *p_rf, *p_w1t, *p_w2t, *p_rw1t;
    float *p_vf, *p_h2;
    cudaGetSymbolAddress((void**)&p_vcat, g_vcat);
    cudaGetSymbolAddress((void**)&p_h, g_h);
    cudaGetSymbolAddress((void**)&p_vf, g_vf);
    cudaGetSymbolAddress((void**)&p_rf, g_rf);
    cudaGetSymbolAddress((void**)&p_h2, g_h2);
    cudaGetSymbolAddress((void**)&p_w1t, g_w1t);
    cudaGetSymbolAddress((void**)&p_w2t, g_w2t);
    cudaGetSymbolAddress((void**)&p_rw1t, g_rw1t);

    const int thr = 256;

    // 0) weight transpose -> fp16
    wtrans_kernel<<<(int)(((size_t)3 * H * H + thr - 1) / thr), thr>>>(w1, p_w1t, 3 * H, H);
    wtrans_kernel<<<(int)(((size_t)H * H + thr - 1) / thr), thr>>>(w2, p_w2t, H, H);
    wtrans_kernel<<<(int)(((size_t)2 * H * H + thr - 1) / thr), thr>>>(rw1, p_rw1t, 2 * H, H);

    // 1) concat -> fp16
    {
        size_t total4 = (size_t)NROWS * 3 * H / 4;
        concat_kernel<<<(int)((total4 + thr - 1) / thr), thr>>>(sfeat, pfeat, ofeat);
    }
    // 2) h = relu(vcat @ w1 + b1) -> fp16
    {
        cudaFuncSetAttribute(tgemm_kernel<true, false, true>,
                             cudaFuncAttributeMaxDynamicSharedMemorySize, TG_SMEM);
        dim3 grid(H / 128, NROWS / 128);
        tgemm_kernel<true, false, true><<<grid, 256, TG_SMEM>>>(
            p_vcat, p_w1t, b1, p_h, nullptr, 3 * H, H);
    }
    // 3) vf = relu(h @ w2 + b2) -> f32
    {
        cudaFuncSetAttribute(tgemm_kernel<false, true, true>,
                             cudaFuncAttributeMaxDynamicSharedMemorySize, TG_SMEM);
        dim3 grid(H / 128, NROWS / 128);
        tgemm_kernel<false, true, true><<<grid, 256, TG_SMEM>>>(
            p_h, p_w2t, b2, nullptr, p_vf, H, H);
    }
    // 4) streaming attention -> rf fp16
    {
        cudaFuncSetAttribute(attn_kernel, cudaFuncAttributeMaxDynamicSharedMemorySize, A_SMEM);
        attn_kernel<<<NROWS, 256, A_SMEM>>>(p_vf, rel, scats, ocats, p_rf);
    }
    // 5) h2 = relu(rf @ rw1 + rb1) -> f32
    {
        dim3 grid(H / 128, NROWS / 128);
        tgemm_kernel<false, true, true><<<grid, 256, TG_SMEM>>>(
            p_rf, p_rw1t, rb1, nullptr, p_h2, 2 * H, H);
    }
    // 6) plogits = h2 @ rw2 + rb2   (FFMA2 fp32, Nd=69)
    {
        dim3 grid(1, NROWS / 128);
        sgemm_kernel<false><<<grid, 256>>>(p_h2, rw2, rb2, out, NROWS, H, PP);
    }
}